// round 8
// baseline (speedup 1.0000x reference)
#include <cuda_runtime.h>
#include <math.h>

#define NODE_IN 64
#define NODE_OUT 96
#define EDGE_IN 32
#define EDGE_OUT 32
#define D0 128
#define DC 192
#define NCLS 2
#define MAXN 50000
#define MAXE 800000

#define NBLK 296      // 2 CTAs/SM on 148 SMs (GB300 has >=148) -> co-resident
#define NTHR 256

// ---------------- device scratch ----------------
__device__ int   g_deg_in[MAXN];
__device__ int   g_deg_out[MAXN];
__device__ int   g_cursor[MAXN];
__device__ int   g_off[MAXN + 1];
__device__ float g_inv_in[MAXN];
__device__ float g_inv_out[MAXN];
__device__ int   g_csr_src[MAXE];
__device__ int   g_csr_eid[MAXE];
__device__ float g_bufA[(size_t)MAXN * DC];
__device__ float g_bufB[(size_t)MAXN * DC];

__device__ int            g_bar_count;
__device__ volatile int   g_bar_gen;

// ---------------- shared memory union ----------------
struct SmemU {
    union {
        struct { float As[64][33]; float Ws[32][64]; } g;             // gemm tiles
        struct { float We[EDGE_IN * EDGE_OUT]; float be[EDGE_OUT]; float x[8][32]; } e;
        struct { int tmp[NTHR]; int carry; } s;                       // scan
    };
};

// ---------------- grid-wide barrier (all CTAs co-resident) ----------------
__device__ __forceinline__ void gsync() {
    __syncthreads();
    if (threadIdx.x == 0) {
        __threadfence();
        int gen = g_bar_gen;
        if (atomicAdd(&g_bar_count, 1) == (int)gridDim.x - 1) {
            g_bar_count = 0;
            __threadfence();
            g_bar_gen = gen + 1;
        } else {
            while (g_bar_gen == gen) { }
        }
    }
    __syncthreads();
}

// ---------------- tiled GEMM stage (persistent tile loop) ----------------
// C[r, coff+c] = relu(A[r,:]@W[:,c] + bias[c]); A row-major stride din, C stride ldc.
__device__ void gemm_stage(const float* __restrict__ A, const float* __restrict__ W,
                           const float* __restrict__ bias, float* __restrict__ C,
                           int nrows, int din, int dout, int ldc, int coff, SmemU* sm) {
    const int BM = 64, BN = 64, BK = 32;
    int tid = threadIdx.x;
    int tx = tid & 15, ty = tid >> 4;
    int tilesX = (dout + BN - 1) / BN;
    int tilesY = (nrows + BM - 1) / BM;
    int numTiles = tilesX * tilesY;

    for (int t = blockIdx.x; t < numTiles; t += gridDim.x) {
        int bx = t % tilesX, by = t / tilesX;
        int row0 = by * BM, col0 = bx * BN;

        float acc[4][4];
        #pragma unroll
        for (int i = 0; i < 4; i++)
            #pragma unroll
            for (int j = 0; j < 4; j++) acc[i][j] = 0.f;

        for (int k0 = 0; k0 < din; k0 += BK) {
            int ka = tid & 31, ma = tid >> 5;
            #pragma unroll
            for (int i = 0; i < 8; i++) {
                int m = ma + i * 8;
                int r = row0 + m;
                sm->g.As[m][ka] = (r < nrows) ? A[(size_t)r * din + k0 + ka] : 0.f;
            }
            int nw = tid & 63, kw0 = tid >> 6;
            #pragma unroll
            for (int i = 0; i < 8; i++) {
                int k = kw0 + i * 4;
                int cc = col0 + nw;
                sm->g.Ws[k][nw] = (cc < dout) ? W[(size_t)(k0 + k) * dout + cc] : 0.f;
            }
            __syncthreads();
            #pragma unroll
            for (int k = 0; k < BK; k++) {
                float a[4], b[4];
                #pragma unroll
                for (int i = 0; i < 4; i++) a[i] = sm->g.As[ty * 4 + i][k];
                #pragma unroll
                for (int j = 0; j < 4; j++) b[j] = sm->g.Ws[k][tx * 4 + j];
                #pragma unroll
                for (int i = 0; i < 4; i++)
                    #pragma unroll
                    for (int j = 0; j < 4; j++)
                        acc[i][j] += a[i] * b[j];
            }
            __syncthreads();
        }
        #pragma unroll
        for (int i = 0; i < 4; i++) {
            int r = row0 + ty * 4 + i;
            if (r >= nrows) continue;
            #pragma unroll
            for (int j = 0; j < 4; j++) {
                int cc = col0 + tx * 4 + j;
                if (cc < dout)
                    C[(size_t)r * ldc + coff + cc] = fmaxf(acc[i][j] + bias[cc], 0.f);
            }
        }
        __syncthreads();   // protect smem before next tile's loads
    }
}

// ---------------- fused persistent kernel ----------------
__global__ void __launch_bounds__(NTHR, 2)
fused_gnn(const float* __restrict__ node_feats, const float* __restrict__ edge_feats,
          const float* __restrict__ Wn, const float* __restrict__ bn,
          const float* __restrict__ We, const float* __restrict__ be,
          const float* __restrict__ Wc0, const float* __restrict__ bc0,
          const float* __restrict__ Wc1, const float* __restrict__ bc1,
          const float* __restrict__ Wl0, const float* __restrict__ bl0,
          const float* __restrict__ Wo, const float* __restrict__ bo,
          const int* __restrict__ src, const int* __restrict__ dst,
          float* __restrict__ out, int n, int e) {
    __shared__ SmemU sm;
    int tid = threadIdx.x;
    int gtid = blockIdx.x * NTHR + tid;
    int gstride = gridDim.x * NTHR;
    int w = tid >> 5, lane = tid & 31;
    int warp_g = blockIdx.x * 8 + w;
    int warps_total = gridDim.x * 8;

    // ---- stage 1: zero degrees ----
    for (int i = gtid; i < n; i += gstride) { g_deg_in[i] = 0; g_deg_out[i] = 0; }
    gsync();

    // ---- stage 2: degree histogram ----
    for (int i = gtid; i < e; i += gstride) {
        atomicAdd(&g_deg_in[dst[i]], 1);
        atomicAdd(&g_deg_out[src[i]], 1);
    }
    gsync();

    // ---- stage 3: inv factors + CSR offsets (scan by CTA 0) ----
    for (int i = gtid; i < n; i += gstride) {
        int di = g_deg_in[i], dn = g_deg_out[i];
        g_inv_in[i]  = rsqrtf((float)(di > 1 ? di : 1));
        g_inv_out[i] = rsqrtf((float)(dn > 1 ? dn : 1));
    }
    if (blockIdx.x == 0) {
        if (tid == 0) sm.s.carry = 0;
        __syncthreads();
        for (int base = 0; base < n; base += NTHR) {
            int i = base + tid;
            int v = (i < n) ? g_deg_in[i] : 0;
            sm.s.tmp[tid] = v;
            __syncthreads();
            for (int ofs = 1; ofs < NTHR; ofs <<= 1) {
                int cur = sm.s.tmp[tid];
                int add = (tid >= ofs) ? sm.s.tmp[tid - ofs] : 0;
                __syncthreads();
                sm.s.tmp[tid] = cur + add;
                __syncthreads();
            }
            int incl = sm.s.tmp[tid];
            int c = sm.s.carry;
            if (i < n) { g_off[i] = c + incl - v; g_cursor[i] = c + incl - v; }
            __syncthreads();
            if (tid == NTHR - 1) sm.s.carry = c + incl;
            __syncthreads();
        }
        if (tid == 0) g_off[n] = e;
    }
    gsync();

    // ---- stage 4: CSR fill ----
    for (int i = gtid; i < e; i += gstride) {
        int d = dst[i];
        int p = atomicAdd(&g_cursor[d], 1);
        g_csr_src[p] = src[i];
        g_csr_eid[p] = i;
    }
    gsync();

    // ---- stage 5: node embedding GEMM -> bufA cols 32..127 ----
    gemm_stage(node_feats, Wn, bn, g_bufA, n, NODE_IN, NODE_OUT, D0, EDGE_OUT, &sm);
    __syncthreads();

    // ---- stage 5b: edge aggregation -> bufA cols 0..31 ----
    for (int i = tid; i < EDGE_IN * EDGE_OUT; i += NTHR) sm.e.We[i] = We[i];
    if (tid < EDGE_OUT) sm.e.be[tid] = be[tid];
    __syncthreads();
    for (int v = warp_g; v < n; v += warps_total) {
        int start = g_off[v], end = g_off[v + 1];
        float acc = 0.f;
        for (int p = start; p < end; p++) {
            int eid = g_csr_eid[p];
            sm.e.x[w][lane] = edge_feats[(size_t)eid * EDGE_IN + lane];
            __syncwarp();
            #pragma unroll
            for (int k = 0; k < EDGE_IN; k++)
                acc += sm.e.x[w][k] * sm.e.We[k * EDGE_OUT + lane];
            __syncwarp();
        }
        int c = end - start;
        float o = (c > 0) ? (acc / (float)c + sm.e.be[lane]) : 0.f;
        g_bufA[(size_t)v * D0 + lane] = fmaxf(o, 0.f);
    }
    gsync();

    // ---- stage 6: conv0 aggregation (d=128): bufA -> bufB ----
    for (int v = warp_g; v < n; v += warps_total) {
        int start = g_off[v], end = g_off[v + 1];
        float acc[4] = {0.f, 0.f, 0.f, 0.f};
        for (int p = start; p < end; p++) {
            int s = g_csr_src[p];
            float wgt = g_inv_out[s];
            const float* hp = g_bufA + (size_t)s * D0;
            #pragma unroll
            for (int i = 0; i < 4; i++)
                acc[i] += hp[lane + 32 * i] * wgt;
        }
        float wi = g_inv_in[v];
        #pragma unroll
        for (int i = 0; i < 4; i++)
            g_bufB[(size_t)v * D0 + lane + 32 * i] = acc[i] * wi;
    }
    gsync();

    // ---- stage 7: conv0 GEMM 128->192: bufB -> bufA ----
    gemm_stage(g_bufB, Wc0, bc0, g_bufA, n, D0, DC, DC, 0, &sm);
    gsync();

    // ---- stage 8: conv1 aggregation (d=192): bufA -> bufB ----
    for (int v = warp_g; v < n; v += warps_total) {
        int start = g_off[v], end = g_off[v + 1];
        float acc[6] = {0.f, 0.f, 0.f, 0.f, 0.f, 0.f};
        for (int p = start; p < end; p++) {
            int s = g_csr_src[p];
            float wgt = g_inv_out[s];
            const float* hp = g_bufA + (size_t)s * DC;
            #pragma unroll
            for (int i = 0; i < 6; i++)
                acc[i] += hp[lane + 32 * i] * wgt;
        }
        float wi = g_inv_in[v];
        #pragma unroll
        for (int i = 0; i < 6; i++)
            g_bufB[(size_t)v * DC + lane + 32 * i] = acc[i] * wi;
    }
    gsync();

    // ---- stage 9: conv1 GEMM 192->192: bufB -> bufA ----
    gemm_stage(g_bufB, Wc1, bc1, g_bufA, n, DC, DC, DC, 0, &sm);
    gsync();

    // ---- stage 10: linear 192->192: bufA -> bufB ----
    gemm_stage(g_bufA, Wl0, bl0, g_bufB, n, DC, DC, DC, 0, &sm);
    gsync();

    // ---- stage 11: output head 192->2 ----
    for (int v = warp_g; v < n; v += warps_total) {
        const float* hp = g_bufB + (size_t)v * DC;
        float a0 = 0.f, a1 = 0.f;
        #pragma unroll
        for (int i = 0; i < DC / 32; i++) {
            int k = lane + 32 * i;
            float h = hp[k];
            a0 += h * Wo[k * 2 + 0];
            a1 += h * Wo[k * 2 + 1];
        }
        #pragma unroll
        for (int o = 16; o; o >>= 1) {
            a0 += __shfl_xor_sync(0xffffffffu, a0, o);
            a1 += __shfl_xor_sync(0xffffffffu, a1, o);
        }
        if (lane == 0) {
            out[(size_t)v * 2 + 0] = a0 + bo[0];
            out[(size_t)v * 2 + 1] = a1 + bo[1];
        }
    }
}

// ---------------- launch: ONE kernel ----------------
extern "C" void kernel_launch(void* const* d_in, const int* in_sizes, int n_in,
                              void* d_out, int out_size) {
    const float* node_feats = (const float*)d_in[0];
    const float* edge_feats = (const float*)d_in[1];
    const float* Wn  = (const float*)d_in[2];
    const float* bn  = (const float*)d_in[3];
    const float* We  = (const float*)d_in[4];
    const float* be  = (const float*)d_in[5];
    const float* Wc0 = (const float*)d_in[6];
    const float* bc0 = (const float*)d_in[7];
    const float* Wc1 = (const float*)d_in[8];
    const float* bc1 = (const float*)d_in[9];
    const float* Wl0 = (const float*)d_in[10];
    const float* bl0 = (const float*)d_in[11];
    const float* Wo  = (const float*)d_in[12];
    const float* bo  = (const float*)d_in[13];
    const int*   src = (const int*)d_in[14];
    const int*   dst = (const int*)d_in[15];
    float* out = (float*)d_out;

    int n = in_sizes[0] / NODE_IN;   // 50000
    int e = in_sizes[14];            // 800000

    fused_gnn<<<NBLK, NTHR>>>(node_feats, edge_feats, Wn, bn, We, be,
                              Wc0, bc0, Wc1, bc1, Wl0, bl0, Wo, bo,
                              src, dst, out, n, e);
}

// round 12
// speedup vs baseline: 1.6655x; 1.6655x over previous
#include <cuda_runtime.h>
#include <math.h>

#define NODE_IN 64
#define NODE_OUT 96
#define EDGE_IN 32
#define EDGE_OUT 32
#define D0 128
#define DC 192
#define NCLS 2
#define MAXN 50000
#define MAXE 800000

#define NBLK 296      // 2 CTAs/SM x 148 SMs -> co-resident (grid barrier safe)
#define NTHR 256

// ---------------- device scratch ----------------
__device__ int   g_deg_in[MAXN];
__device__ int   g_deg_out[MAXN];
__device__ int   g_cursor[MAXN];
__device__ int   g_off[MAXN + 1];
__device__ float g_inv_in[MAXN];
__device__ float g_inv_out[MAXN];
__device__ int   g_csr_src[MAXE];
__device__ int   g_csr_eid[MAXE];
__device__ float g_bufA[(size_t)MAXN * DC];
__device__ float g_bufB[(size_t)MAXN * DC];
__device__ int   g_bsum[512];
__device__ int   g_bpre[512];

__device__ int            g_bar_count;
__device__ volatile int   g_bar_gen;

// ---------------- shared memory ----------------
struct SmemU {
    union {
        struct { float As[16][132]; float Ws[16][68]; } g;   // gemm tiles (k-major)
        struct { int tmp[NTHR]; } s;                         // scan
    };
};

// ---------------- grid-wide barrier ----------------
__device__ __forceinline__ void gsync() {
    __syncthreads();
    if (threadIdx.x == 0) {
        __threadfence();
        int gen = g_bar_gen;
        if (atomicAdd(&g_bar_count, 1) == (int)gridDim.x - 1) {
            g_bar_count = 0;
            __threadfence();
            g_bar_gen = gen + 1;
        } else {
            while (g_bar_gen == gen) { }
        }
    }
    __syncthreads();
}

// ---------------- tiled GEMM stage: 128x64x16, 8x4 micro-tile ----------------
// C[r, coff+c] = relu(A[r,:]@W[:,c] + bias[c]); if maskdeg and deg_in[r]==0 -> 0.
// Requires din % 16 == 0 (holds: 32, 64, 128, 192).
__device__ void gemm_stage(const float* __restrict__ A, const float* __restrict__ W,
                           const float* __restrict__ bias, float* __restrict__ C,
                           int nrows, int din, int dout, int ldc, int coff,
                           int maskdeg, SmemU* sm) {
    const int BM = 128, BN = 64, BK = 16;
    int tid = threadIdx.x;
    int tx = tid & 15, ty = tid >> 4;        // tx: N (4 cols), ty: M (8 rows)
    int tilesX = (dout + BN - 1) / BN;
    int tilesY = (nrows + BM - 1) / BM;
    int numTiles = tilesX * tilesY;

    int la_m = tid >> 2;                     // 0..63 (two passes -> 128 rows)
    int la_k = (tid & 3) * 4;                // 0,4,8,12
    int lb_k = tid >> 4;                     // 0..15
    int lb_c = (tid & 15) * 4;               // 0..60

    for (int t = blockIdx.x; t < numTiles; t += gridDim.x) {
        int bx = t % tilesX, by = t / tilesX;
        int row0 = by * BM, col0 = bx * BN;

        float acc[8][4];
        #pragma unroll
        for (int i = 0; i < 8; i++)
            #pragma unroll
            for (int j = 0; j < 4; j++) acc[i][j] = 0.f;

        for (int k0 = 0; k0 < din; k0 += BK) {
            // A tile -> As[k][m] (transposed store)
            #pragma unroll
            for (int pass = 0; pass < 2; pass++) {
                int m = la_m + pass * 64;
                int r = row0 + m;
                float4 av = make_float4(0.f, 0.f, 0.f, 0.f);
                if (r < nrows) av = *(const float4*)&A[(size_t)r * din + k0 + la_k];
                sm->g.As[la_k + 0][m] = av.x;
                sm->g.As[la_k + 1][m] = av.y;
                sm->g.As[la_k + 2][m] = av.z;
                sm->g.As[la_k + 3][m] = av.w;
            }
            // W tile -> Ws[k][c]
            {
                int cc = col0 + lb_c;
                float4 bv = make_float4(0.f, 0.f, 0.f, 0.f);
                if (cc + 3 < dout) bv = *(const float4*)&W[(size_t)(k0 + lb_k) * dout + cc];
                *(float4*)&sm->g.Ws[lb_k][lb_c] = bv;
            }
            __syncthreads();
            #pragma unroll
            for (int k = 0; k < BK; k++) {
                float4 a0 = *(const float4*)&sm->g.As[k][ty * 8];
                float4 a1 = *(const float4*)&sm->g.As[k][ty * 8 + 4];
                float4 b  = *(const float4*)&sm->g.Ws[k][tx * 4];
                float am[8] = {a0.x, a0.y, a0.z, a0.w, a1.x, a1.y, a1.z, a1.w};
                float bv[4] = {b.x, b.y, b.z, b.w};
                #pragma unroll
                for (int i = 0; i < 8; i++)
                    #pragma unroll
                    for (int j = 0; j < 4; j++)
                        acc[i][j] += am[i] * bv[j];
            }
            __syncthreads();
        }
        // epilogue
        #pragma unroll
        for (int i = 0; i < 8; i++) {
            int r = row0 + ty * 8 + i;
            if (r >= nrows) continue;
            float scale = (maskdeg && g_deg_in[r] == 0) ? 0.f : 1.f;
            int cc = col0 + tx * 4;
            if (cc + 3 < dout) {
                float4 v;
                v.x = scale * fmaxf(acc[i][0] + bias[cc + 0], 0.f);
                v.y = scale * fmaxf(acc[i][1] + bias[cc + 1], 0.f);
                v.z = scale * fmaxf(acc[i][2] + bias[cc + 2], 0.f);
                v.w = scale * fmaxf(acc[i][3] + bias[cc + 3], 0.f);
                *(float4*)&C[(size_t)r * ldc + coff + cc] = v;
            } else {
                #pragma unroll
                for (int j = 0; j < 4; j++)
                    if (cc + j < dout)
                        C[(size_t)r * ldc + coff + cc + j] =
                            scale * fmaxf(acc[i][j] + bias[cc + j], 0.f);
            }
        }
        __syncthreads();
    }
}

// ---------------- fused persistent kernel ----------------
__global__ void __launch_bounds__(NTHR, 2)
fused_gnn(const float* __restrict__ node_feats, const float* __restrict__ edge_feats,
          const float* __restrict__ Wn, const float* __restrict__ bn,
          const float* __restrict__ We, const float* __restrict__ be,
          const float* __restrict__ Wc0, const float* __restrict__ bc0,
          const float* __restrict__ Wc1, const float* __restrict__ bc1,
          const float* __restrict__ Wl0, const float* __restrict__ bl0,
          const float* __restrict__ Wo, const float* __restrict__ bo,
          const int* __restrict__ src, const int* __restrict__ dst,
          float* __restrict__ out, int n, int e) {
    __shared__ SmemU sm;
    int tid = threadIdx.x;
    int gtid = blockIdx.x * NTHR + tid;
    int gstride = gridDim.x * NTHR;
    int w = tid >> 5, lane = tid & 31;
    int warp_g = blockIdx.x * 8 + w;
    int warps_total = gridDim.x * 8;
    int nchunks = (n + NTHR - 1) / NTHR;

    // ---- 1: zero degrees ----
    for (int i = gtid; i < n; i += gstride) { g_deg_in[i] = 0; g_deg_out[i] = 0; }
    gsync();

    // ---- 2: degree histogram ----
    for (int i = gtid; i < e; i += gstride) {
        atomicAdd(&g_deg_in[dst[i]], 1);
        atomicAdd(&g_deg_out[src[i]], 1);
    }
    gsync();

    // ---- 3: inv factors + per-chunk local scan ----
    for (int i = gtid; i < n; i += gstride) {
        int di = g_deg_in[i], dn = g_deg_out[i];
        g_inv_in[i]  = rsqrtf((float)(di > 1 ? di : 1));
        g_inv_out[i] = rsqrtf((float)(dn > 1 ? dn : 1));
    }
    if ((int)blockIdx.x < nchunks) {
        int i = blockIdx.x * NTHR + tid;
        int v = (i < n) ? g_deg_in[i] : 0;
        sm.s.tmp[tid] = v;
        __syncthreads();
        for (int ofs = 1; ofs < NTHR; ofs <<= 1) {
            int cur = sm.s.tmp[tid];
            int add = (tid >= ofs) ? sm.s.tmp[tid - ofs] : 0;
            __syncthreads();
            sm.s.tmp[tid] = cur + add;
            __syncthreads();
        }
        if (i < n) g_off[i] = sm.s.tmp[tid] - v;       // local exclusive
        if (tid == NTHR - 1) g_bsum[blockIdx.x] = sm.s.tmp[tid];
    }
    gsync();

    // ---- 4: scan block sums (one warp) ----
    if (blockIdx.x == 0 && w == 0) {
        int carry = 0;
        for (int base = 0; base < nchunks; base += 32) {
            int idx = base + lane;
            int orig = (idx < nchunks) ? g_bsum[idx] : 0;
            int v = orig;
            #pragma unroll
            for (int o = 1; o < 32; o <<= 1) {
                int t = __shfl_up_sync(0xffffffffu, v, o);
                if (lane >= o) v += t;
            }
            if (idx < nchunks) g_bpre[idx] = carry + v - orig;   // exclusive
            carry += __shfl_sync(0xffffffffu, v, 31);
        }
    }
    gsync();

    // ---- 5: add block prefixes ----
    for (int i = gtid; i < n; i += gstride) {
        int o = g_off[i] + g_bpre[i / NTHR];
        g_off[i] = o;
        g_cursor[i] = o;
    }
    if (gtid == 0) g_off[n] = e;
    gsync();

    // ---- 6: CSR fill ----
    for (int i = gtid; i < e; i += gstride) {
        int d = dst[i];
        int p = atomicAdd(&g_cursor[d], 1);
        g_csr_src[p] = src[i];
        g_csr_eid[p] = i;
    }
    gsync();

    // ---- 7: mean edge features -> bufB[v][0..31] (stride 32) ----
    for (int v = warp_g; v < n; v += warps_total) {
        int start = g_off[v], end = g_off[v + 1];
        float acc = 0.f;
        int p = start;
        for (; p + 1 < end; p += 2) {
            int e0 = g_csr_eid[p], e1 = g_csr_eid[p + 1];
            acc += edge_feats[(size_t)e0 * EDGE_IN + lane]
                 + edge_feats[(size_t)e1 * EDGE_IN + lane];
        }
        if (p < end) acc += edge_feats[(size_t)g_csr_eid[p] * EDGE_IN + lane];
        int c = end - start;
        g_bufB[(size_t)v * EDGE_IN + lane] = (c > 0) ? acc / (float)c : 0.f;
    }
    gsync();

    // ---- 8: edge GEMM (32->32, masked) + node GEMM (64->96) -> bufA ----
    gemm_stage(g_bufB, We, be, g_bufA, n, EDGE_IN, EDGE_OUT, D0, 0, 1, &sm);
    gemm_stage(node_feats, Wn, bn, g_bufA, n, NODE_IN, NODE_OUT, D0, EDGE_OUT, 0, &sm);
    gsync();

    // ---- 9: conv0 aggregation (d=128): bufA -> bufB ----
    for (int v = warp_g; v < n; v += warps_total) {
        int start = g_off[v], end = g_off[v + 1];
        float acc[4] = {0.f, 0.f, 0.f, 0.f};
        int p = start;
        for (; p + 1 < end; p += 2) {
            int s0 = g_csr_src[p], s1 = g_csr_src[p + 1];
            float w0 = g_inv_out[s0], w1 = g_inv_out[s1];
            const float* h0p = g_bufA + (size_t)s0 * D0;
            const float* h1p = g_bufA + (size_t)s1 * D0;
            #pragma unroll
            for (int i = 0; i < 4; i++)
                acc[i] += h0p[lane + 32 * i] * w0 + h1p[lane + 32 * i] * w1;
        }
        if (p < end) {
            int s0 = g_csr_src[p];
            float w0 = g_inv_out[s0];
            const float* h0p = g_bufA + (size_t)s0 * D0;
            #pragma unroll
            for (int i = 0; i < 4; i++)
                acc[i] += h0p[lane + 32 * i] * w0;
        }
        float wi = g_inv_in[v];
        #pragma unroll
        for (int i = 0; i < 4; i++)
            g_bufB[(size_t)v * D0 + lane + 32 * i] = acc[i] * wi;
    }
    gsync();

    // ---- 10: conv0 GEMM 128->192: bufB -> bufA ----
    gemm_stage(g_bufB, Wc0, bc0, g_bufA, n, D0, DC, DC, 0, 0, &sm);
    gsync();

    // ---- 11: conv1 aggregation (d=192): bufA -> bufB ----
    for (int v = warp_g; v < n; v += warps_total) {
        int start = g_off[v], end = g_off[v + 1];
        float acc[6] = {0.f, 0.f, 0.f, 0.f, 0.f, 0.f};
        int p = start;
        for (; p + 1 < end; p += 2) {
            int s0 = g_csr_src[p], s1 = g_csr_src[p + 1];
            float w0 = g_inv_out[s0], w1 = g_inv_out[s1];
            const float* h0p = g_bufA + (size_t)s0 * DC;
            const float* h1p = g_bufA + (size_t)s1 * DC;
            #pragma unroll
            for (int i = 0; i < 6; i++)
                acc[i] += h0p[lane + 32 * i] * w0 + h1p[lane + 32 * i] * w1;
        }
        if (p < end) {
            int s0 = g_csr_src[p];
            float w0 = g_inv_out[s0];
            const float* h0p = g_bufA + (size_t)s0 * DC;
            #pragma unroll
            for (int i = 0; i < 6; i++)
                acc[i] += h0p[lane + 32 * i] * w0;
        }
        float wi = g_inv_in[v];
        #pragma unroll
        for (int i = 0; i < 6; i++)
            g_bufB[(size_t)v * DC + lane + 32 * i] = acc[i] * wi;
    }
    gsync();

    // ---- 12: conv1 GEMM 192->192: bufB -> bufA ----
    gemm_stage(g_bufB, Wc1, bc1, g_bufA, n, DC, DC, DC, 0, 0, &sm);
    gsync();

    // ---- 13: linear 192->192: bufA -> bufB ----
    gemm_stage(g_bufA, Wl0, bl0, g_bufB, n, DC, DC, DC, 0, 0, &sm);
    gsync();

    // ---- 14: output head 192->2 ----
    for (int v = warp_g; v < n; v += warps_total) {
        const float* hp = g_bufB + (size_t)v * DC;
        float a0 = 0.f, a1 = 0.f;
        #pragma unroll
        for (int i = 0; i < DC / 32; i++) {
            int k = lane + 32 * i;
            float h = hp[k];
            a0 += h * Wo[k * 2 + 0];
            a1 += h * Wo[k * 2 + 1];
        }
        #pragma unroll
        for (int o = 16; o; o >>= 1) {
            a0 += __shfl_xor_sync(0xffffffffu, a0, o);
            a1 += __shfl_xor_sync(0xffffffffu, a1, o);
        }
        if (lane == 0) {
            out[(size_t)v * 2 + 0] = a0 + bo[0];
            out[(size_t)v * 2 + 1] = a1 + bo[1];
        }
    }
}

// ---------------- launch: ONE kernel ----------------
extern "C" void kernel_launch(void* const* d_in, const int* in_sizes, int n_in,
                              void* d_out, int out_size) {
    const float* node_feats = (const float*)d_in[0];
    const float* edge_feats = (const float*)d_in[1];
    const float* Wn  = (const float*)d_in[2];
    const float* bn  = (const float*)d_in[3];
    const float* We  = (const float*)d_in[4];
    const float* be  = (const float*)d_in[5];
    const float* Wc0 = (const float*)d_in[6];
    const float* bc0 = (const float*)d_in[7];
    const float* Wc1 = (const float*)d_in[8];
    const float* bc1 = (const float*)d_in[9];
    const float* Wl0 = (const float*)d_in[10];
    const float* bl0 = (const float*)d_in[11];
    const float* Wo  = (const float*)d_in[12];
    const float* bo  = (const float*)d_in[13];
    const int*   src = (const int*)d_in[14];
    const int*   dst = (const int*)d_in[15];
    float* out = (float*)d_out;

    int n = in_sizes[0] / NODE_IN;   // 50000
    int e = in_sizes[14];            // 800000

    fused_gnn<<<NBLK, NTHR>>>(node_feats, edge_feats, Wn, bn, We, be,
                              Wc0, bc0, Wc1, bc1, Wl0, bl0, Wo, bo,
                              src, dst, out, n, e);
}

// round 13
// speedup vs baseline: 2.1575x; 1.2954x over previous
#include <cuda_runtime.h>
#include <math.h>

#define NODE_IN 64
#define NODE_OUT 96
#define EDGE_IN 32
#define EDGE_OUT 32
#define D0 128
#define DC 192
#define NCLS 2
#define MAXN 50000
#define MAXE 800000

#define NBLK 296      // 2 CTAs/SM x 148 SMs -> co-resident (grid barrier safe)
#define NTHR 256

#define APITCH 20     // A smem pitch (floats): r*20 mod 32 spaced by 4 -> conflict-free
#define BPITCH 72     // B smem pitch (floats): k*72 mod 32 = 8k -> conflict-free

// ---------------- device scratch ----------------
__device__ int   g_deg_in[MAXN];
__device__ int   g_deg_out[MAXN];
__device__ int   g_cursor[MAXN];
__device__ int   g_off[MAXN + 1];
__device__ float g_inv_in[MAXN];
__device__ float g_inv_out[MAXN];
__device__ int   g_csr_src[MAXE];
__device__ int   g_csr_eid[MAXE];
__device__ float g_bufA[(size_t)MAXN * DC];
__device__ float g_bufB[(size_t)MAXN * DC];
__device__ int   g_bsum[512];
__device__ int   g_bpre[512];

__device__ int            g_bar_count;
__device__ volatile int   g_bar_gen;

// ---------------- shared memory ----------------
struct SmemU {
    union {
        struct { float As[128 * APITCH]; float Bs[16 * BPITCH]; } g;  // 14.8 KB
        struct { int tmp[NTHR]; } s;
    };
};

// ---------------- grid-wide barrier ----------------
__device__ __forceinline__ void gsync() {
    __syncthreads();
    if (threadIdx.x == 0) {
        __threadfence();
        int gen = g_bar_gen;
        if (atomicAdd(&g_bar_count, 1) == (int)gridDim.x - 1) {
            g_bar_count = 0;
            __threadfence();
            g_bar_gen = gen + 1;
        } else {
            while (g_bar_gen == gen) { }
        }
    }
    __syncthreads();
}

__device__ __forceinline__ float tf32r(float x) {
    float y;
    asm("cvt.rna.tf32.f32 %0, %1;" : "=f"(y) : "f"(x));
    return y;
}

__device__ __forceinline__ void mma_tf32(float c[4], const unsigned a[4], const unsigned b[2]) {
    asm volatile(
        "mma.sync.aligned.m16n8k8.row.col.f32.tf32.tf32.f32 "
        "{%0,%1,%2,%3}, {%4,%5,%6,%7}, {%8,%9}, {%0,%1,%2,%3};"
        : "+f"(c[0]), "+f"(c[1]), "+f"(c[2]), "+f"(c[3])
        : "r"(a[0]), "r"(a[1]), "r"(a[2]), "r"(a[3]), "r"(b[0]), "r"(b[1]));
}

// ---------------- TF32 tensor-core GEMM stage ----------------
// C[r, coff+c] = relu(A[r,:]@W[:,c] + bias[c]); maskdeg: zero rows with deg_in==0.
// din % 16 == 0; dout % 8 == 0. CTA tile 128x64, warp tile 32x32, k-step 16.
__device__ void gemm_stage(const float* __restrict__ A, const float* __restrict__ W,
                           const float* __restrict__ bias, float* __restrict__ C,
                           int nrows, int din, int dout, int ldc, int coff,
                           int maskdeg, SmemU* sm) {
    const int BM = 128, BN = 64, BK = 16;
    int tid = threadIdx.x;
    int w = tid >> 5, lane = tid & 31;
    int tq = lane >> 2, tr = lane & 3;          // quad-row, quad-col
    int woff = (w & 3) * 32;                    // warp M offset
    int noff = (w >> 2) * 32;                   // warp N offset

    int tilesX = (dout + BN - 1) / BN;
    int tilesY = (nrows + BM - 1) / BM;
    int numTiles = tilesX * tilesY;

    // GMEM load indices
    int la_r = tid >> 2;                        // 0..63 (+64 on pass 1)
    int la_k = (tid & 3) * 4;
    int lb_k = tid >> 4;                        // 0..15
    int lb_c = (tid & 15) * 4;

    float* As = sm->g.As;
    float* Bs = sm->g.Bs;

    for (int t = blockIdx.x; t < numTiles; t += gridDim.x) {
        int bx = t % tilesX, by = t / tilesX;
        int row0 = by * BM, col0 = bx * BN;

        float acc[2][4][4];
        #pragma unroll
        for (int m = 0; m < 2; m++)
            #pragma unroll
            for (int j = 0; j < 4; j++)
                #pragma unroll
                for (int c = 0; c < 4; c++) acc[m][j][c] = 0.f;

        float4 pa[2], pb;
        // prefetch first k-tile
        {
            #pragma unroll
            for (int pass = 0; pass < 2; pass++) {
                int r = row0 + la_r + 64 * pass;
                pa[pass] = (r < nrows) ? *(const float4*)&A[(size_t)r * din + la_k]
                                       : make_float4(0.f, 0.f, 0.f, 0.f);
            }
            int cc = col0 + lb_c;
            pb = (cc + 3 < dout) ? *(const float4*)&W[(size_t)lb_k * dout + cc]
                                 : make_float4(0.f, 0.f, 0.f, 0.f);
        }

        for (int k0 = 0; k0 < din; k0 += BK) {
            __syncthreads();   // previous compute done; smem free
            // store prefetched tile (tf32-rounded)
            #pragma unroll
            for (int pass = 0; pass < 2; pass++) {
                int m = la_r + 64 * pass;
                As[m * APITCH + la_k + 0] = tf32r(pa[pass].x);
                As[m * APITCH + la_k + 1] = tf32r(pa[pass].y);
                As[m * APITCH + la_k + 2] = tf32r(pa[pass].z);
                As[m * APITCH + la_k + 3] = tf32r(pa[pass].w);
            }
            Bs[lb_k * BPITCH + lb_c + 0] = tf32r(pb.x);
            Bs[lb_k * BPITCH + lb_c + 1] = tf32r(pb.y);
            Bs[lb_k * BPITCH + lb_c + 2] = tf32r(pb.z);
            Bs[lb_k * BPITCH + lb_c + 3] = tf32r(pb.w);
            __syncthreads();

            // prefetch next k-tile (overlaps with compute below)
            if (k0 + BK < din) {
                #pragma unroll
                for (int pass = 0; pass < 2; pass++) {
                    int r = row0 + la_r + 64 * pass;
                    pa[pass] = (r < nrows)
                        ? *(const float4*)&A[(size_t)r * din + k0 + BK + la_k]
                        : make_float4(0.f, 0.f, 0.f, 0.f);
                }
                int cc = col0 + lb_c;
                pb = (cc + 3 < dout)
                    ? *(const float4*)&W[(size_t)(k0 + BK + lb_k) * dout + cc]
                    : make_float4(0.f, 0.f, 0.f, 0.f);
            }

            // compute: 2 k-chunks of 8
            #pragma unroll
            for (int kc = 0; kc < BK; kc += 8) {
                unsigned a[2][4], b[4][2];
                #pragma unroll
                for (int m = 0; m < 2; m++) {
                    int br = woff + 16 * m + tq;
                    a[m][0] = __float_as_uint(As[br * APITCH + kc + tr]);
                    a[m][1] = __float_as_uint(As[(br + 8) * APITCH + kc + tr]);
                    a[m][2] = __float_as_uint(As[br * APITCH + kc + tr + 4]);
                    a[m][3] = __float_as_uint(As[(br + 8) * APITCH + kc + tr + 4]);
                }
                #pragma unroll
                for (int j = 0; j < 4; j++) {
                    int bn = noff + 8 * j + tq;
                    b[j][0] = __float_as_uint(Bs[(kc + tr) * BPITCH + bn]);
                    b[j][1] = __float_as_uint(Bs[(kc + tr + 4) * BPITCH + bn]);
                }
                #pragma unroll
                for (int m = 0; m < 2; m++)
                    #pragma unroll
                    for (int j = 0; j < 4; j++)
                        mma_tf32(acc[m][j], a[m], b[j]);
            }
        }
        __syncthreads();   // protect smem before next tile

        // epilogue: c0,c1 -> (row tq, cols 2tr,2tr+1); c2,c3 -> row tq+8
        #pragma unroll
        for (int m = 0; m < 2; m++) {
            #pragma unroll
            for (int j = 0; j < 4; j++) {
                int cg = col0 + noff + 8 * j + 2 * tr;
                if (cg >= dout) continue;     // dout % 8 == 0 -> pair fully in/out
                float b0 = bias[cg], b1 = bias[cg + 1];
                int rg = row0 + woff + 16 * m + tq;
                #pragma unroll
                for (int h = 0; h < 2; h++) {
                    int r = rg + 8 * h;
                    if (r < nrows) {
                        float scale = (maskdeg && g_deg_in[r] == 0) ? 0.f : 1.f;
                        float2 v;
                        v.x = scale * fmaxf(acc[m][j][2 * h + 0] + b0, 0.f);
                        v.y = scale * fmaxf(acc[m][j][2 * h + 1] + b1, 0.f);
                        *(float2*)&C[(size_t)r * ldc + coff + cg] = v;
                    }
                }
            }
        }
    }
}

// ---------------- fused persistent kernel ----------------
__global__ void __launch_bounds__(NTHR, 2)
fused_gnn(const float* __restrict__ node_feats, const float* __restrict__ edge_feats,
          const float* __restrict__ Wn, const float* __restrict__ bn,
          const float* __restrict__ We, const float* __restrict__ be,
          const float* __restrict__ Wc0, const float* __restrict__ bc0,
          const float* __restrict__ Wc1, const float* __restrict__ bc1,
          const float* __restrict__ Wl0, const float* __restrict__ bl0,
          const float* __restrict__ Wo, const float* __restrict__ bo,
          const int* __restrict__ src, const int* __restrict__ dst,
          float* __restrict__ out, int n, int e) {
    __shared__ SmemU sm;
    int tid = threadIdx.x;
    int gtid = blockIdx.x * NTHR + tid;
    int gstride = gridDim.x * NTHR;
    int w = tid >> 5, lane = tid & 31;
    int warp_g = blockIdx.x * 8 + w;
    int warps_total = gridDim.x * 8;
    int nchunks = (n + NTHR - 1) / NTHR;

    // ---- 1: zero degrees ----
    for (int i = gtid; i < n; i += gstride) { g_deg_in[i] = 0; g_deg_out[i] = 0; }
    gsync();

    // ---- 2: degree histogram ----
    for (int i = gtid; i < e; i += gstride) {
        atomicAdd(&g_deg_in[dst[i]], 1);
        atomicAdd(&g_deg_out[src[i]], 1);
    }
    gsync();

    // ---- 3: inv factors + per-chunk local scan ----
    for (int i = gtid; i < n; i += gstride) {
        int di = g_deg_in[i], dn = g_deg_out[i];
        g_inv_in[i]  = rsqrtf((float)(di > 1 ? di : 1));
        g_inv_out[i] = rsqrtf((float)(dn > 1 ? dn : 1));
    }
    if ((int)blockIdx.x < nchunks) {
        int i = blockIdx.x * NTHR + tid;
        int v = (i < n) ? g_deg_in[i] : 0;
        sm.s.tmp[tid] = v;
        __syncthreads();
        for (int ofs = 1; ofs < NTHR; ofs <<= 1) {
            int cur = sm.s.tmp[tid];
            int add = (tid >= ofs) ? sm.s.tmp[tid - ofs] : 0;
            __syncthreads();
            sm.s.tmp[tid] = cur + add;
            __syncthreads();
        }
        if (i < n) g_off[i] = sm.s.tmp[tid] - v;       // local exclusive
        if (tid == NTHR - 1) g_bsum[blockIdx.x] = sm.s.tmp[tid];
    }
    gsync();

    // ---- 4: scan block sums (one warp) ----
    if (blockIdx.x == 0 && w == 0) {
        int carry = 0;
        for (int base = 0; base < nchunks; base += 32) {
            int idx = base + lane;
            int orig = (idx < nchunks) ? g_bsum[idx] : 0;
            int v = orig;
            #pragma unroll
            for (int o = 1; o < 32; o <<= 1) {
                int t = __shfl_up_sync(0xffffffffu, v, o);
                if (lane >= o) v += t;
            }
            if (idx < nchunks) g_bpre[idx] = carry + v - orig;   // exclusive
            carry += __shfl_sync(0xffffffffu, v, 31);
        }
    }
    gsync();

    // ---- 5: add block prefixes ----
    for (int i = gtid; i < n; i += gstride) {
        int o = g_off[i] + g_bpre[i / NTHR];
        g_off[i] = o;
        g_cursor[i] = o;
    }
    if (gtid == 0) g_off[n] = e;
    gsync();

    // ---- 6: CSR fill ----
    for (int i = gtid; i < e; i += gstride) {
        int d = dst[i];
        int p = atomicAdd(&g_cursor[d], 1);
        g_csr_src[p] = src[i];
        g_csr_eid[p] = i;
    }
    gsync();

    // ---- 7: mean edge features -> bufB[v][0..31] (stride 32) ----
    for (int v = warp_g; v < n; v += warps_total) {
        int start = g_off[v], end = g_off[v + 1];
        float acc = 0.f;
        int p = start;
        for (; p + 1 < end; p += 2) {
            int e0 = g_csr_eid[p], e1 = g_csr_eid[p + 1];
            acc += edge_feats[(size_t)e0 * EDGE_IN + lane]
                 + edge_feats[(size_t)e1 * EDGE_IN + lane];
        }
        if (p < end) acc += edge_feats[(size_t)g_csr_eid[p] * EDGE_IN + lane];
        int c = end - start;
        g_bufB[(size_t)v * EDGE_IN + lane] = (c > 0) ? acc / (float)c : 0.f;
    }
    gsync();

    // ---- 8: edge GEMM (32->32, masked) + node GEMM (64->96) -> bufA ----
    gemm_stage(g_bufB, We, be, g_bufA, n, EDGE_IN, EDGE_OUT, D0, 0, 1, &sm);
    gemm_stage(node_feats, Wn, bn, g_bufA, n, NODE_IN, NODE_OUT, D0, EDGE_OUT, 0, &sm);
    gsync();

    // ---- 9: conv0 aggregation (d=128): bufA -> bufB ----
    for (int v = warp_g; v < n; v += warps_total) {
        int start = g_off[v], end = g_off[v + 1];
        float acc[4] = {0.f, 0.f, 0.f, 0.f};
        int p = start;
        for (; p + 1 < end; p += 2) {
            int s0 = g_csr_src[p], s1 = g_csr_src[p + 1];
            float w0 = g_inv_out[s0], w1 = g_inv_out[s1];
            const float* h0p = g_bufA + (size_t)s0 * D0;
            const float* h1p = g_bufA + (size_t)s1 * D0;
            #pragma unroll
            for (int i = 0; i < 4; i++)
                acc[i] += h0p[lane + 32 * i] * w0 + h1p[lane + 32 * i] * w1;
        }
        if (p < end) {
            int s0 = g_csr_src[p];
            float w0 = g_inv_out[s0];
            const float* h0p = g_bufA + (size_t)s0 * D0;
            #pragma unroll
            for (int i = 0; i < 4; i++)
                acc[i] += h0p[lane + 32 * i] * w0;
        }
        float wi = g_inv_in[v];
        #pragma unroll
        for (int i = 0; i < 4; i++)
            g_bufB[(size_t)v * D0 + lane + 32 * i] = acc[i] * wi;
    }
    gsync();

    // ---- 10: conv0 GEMM 128->192: bufB -> bufA ----
    gemm_stage(g_bufB, Wc0, bc0, g_bufA, n, D0, DC, DC, 0, 0, &sm);
    gsync();

    // ---- 11: conv1 aggregation (d=192): bufA -> bufB ----
    for (int v = warp_g; v < n; v += warps_total) {
        int start = g_off[v], end = g_off[v + 1];
        float acc[6] = {0.f, 0.f, 0.f, 0.f, 0.f, 0.f};
        int p = start;
        for (; p + 1 < end; p += 2) {
            int s0 = g_csr_src[p], s1 = g_csr_src[p + 1];
            float w0 = g_inv_out[s0], w1 = g_inv_out[s1];
            const float* h0p = g_bufA + (size_t)s0 * DC;
            const float* h1p = g_bufA + (size_t)s1 * DC;
            #pragma unroll
            for (int i = 0; i < 6; i++)
                acc[i] += h0p[lane + 32 * i] * w0 + h1p[lane + 32 * i] * w1;
        }
        if (p < end) {
            int s0 = g_csr_src[p];
            float w0 = g_inv_out[s0];
            const float* h0p = g_bufA + (size_t)s0 * DC;
            #pragma unroll
            for (int i = 0; i < 6; i++)
                acc[i] += h0p[lane + 32 * i] * w0;
        }
        float wi = g_inv_in[v];
        #pragma unroll
        for (int i = 0; i < 6; i++)
            g_bufB[(size_t)v * DC + lane + 32 * i] = acc[i] * wi;
    }
    gsync();

    // ---- 12: conv1 GEMM 192->192: bufB -> bufA ----
    gemm_stage(g_bufB, Wc1, bc1, g_bufA, n, DC, DC, DC, 0, 0, &sm);
    gsync();

    // ---- 13: linear 192->192: bufA -> bufB ----
    gemm_stage(g_bufA, Wl0, bl0, g_bufB, n, DC, DC, DC, 0, 0, &sm);
    gsync();

    // ---- 14: output head 192->2 (exact fp32) ----
    for (int v = warp_g; v < n; v += warps_total) {
        const float* hp = g_bufB + (size_t)v * DC;
        float a0 = 0.f, a1 = 0.f;
        #pragma unroll
        for (int i = 0; i < DC / 32; i++) {
            int k = lane + 32 * i;
            float h = hp[k];
            a0 += h * Wo[k * 2 + 0];
            a1 += h * Wo[k * 2 + 1];
        }
        #pragma unroll
        for (int o = 16; o; o >>= 1) {
            a0 += __shfl_xor_sync(0xffffffffu, a0, o);
            a1 += __shfl_xor_sync(0xffffffffu, a1, o);
        }
        if (lane == 0) {
            out[(size_t)v * 2 + 0] = a0 + bo[0];
            out[(size_t)v * 2 + 1] = a1 + bo[1];
        }
    }
}

// ---------------- launch: ONE kernel ----------------
extern "C" void kernel_launch(void* const* d_in, const int* in_sizes, int n_in,
                              void* d_out, int out_size) {
    const float* node_feats = (const float*)d_in[0];
    const float* edge_feats = (const float*)d_in[1];
    const float* Wn  = (const float*)d_in[2];
    const float* bn  = (const float*)d_in[3];
    const float* We  = (const float*)d_in[4];
    const float* be  = (const float*)d_in[5];
    const float* Wc0 = (const float*)d_in[6];
    const float* bc0 = (const float*)d_in[7];
    const float* Wc1 = (const float*)d_in[8];
    const float* bc1 = (const float*)d_in[9];
    const float* Wl0 = (const float*)d_in[10];
    const float* bl0 = (const float*)d_in[11];
    const float* Wo  = (const float*)d_in[12];
    const float* bo  = (const float*)d_in[13];
    const int*   src = (const int*)d_in[14];
    const int*   dst = (const int*)d_in[15];
    float* out = (float*)d_out;

    int n = in_sizes[0] / NODE_IN;   // 50000
    int e = in_sizes[14];            // 800000

    fused_gnn<<<NBLK, NTHR>>>(node_feats, edge_feats, Wn, bn, We, be,
                              Wc0, bc0, Wc1, bc1, Wl0, bl0, Wo, bo,
                              src, dst, out, n, e);
}

// round 14
// speedup vs baseline: 2.2887x; 1.0608x over previous
#include <cuda_runtime.h>
#include <math.h>

#define NODE_IN 64
#define NODE_OUT 96
#define EDGE_IN 32
#define EDGE_OUT 32
#define D0 128
#define DC 192
#define NCLS 2
#define MAXN 50000
#define MAXE 800000

#define NBLK 296      // 2 CTAs/SM x 148 SMs -> co-resident (grid barrier safe)
#define NTHR 256

#define APITCH 20     // A smem pitch (floats): conflict-free
#define BPITCH 72     // B smem pitch (floats): conflict-free

// ---------------- device scratch ----------------
__device__ int   g_deg_in[MAXN];
__device__ int   g_deg_out[MAXN];
__device__ int   g_cursor[MAXN];
__device__ int   g_off[MAXN + 1];
__device__ float g_inv_in[MAXN];
__device__ float g_inv_out[MAXN];
__device__ int   g_csr_src[MAXE];
__device__ int   g_csr_eid[MAXE];
__device__ float g_csr_w[MAXE];      // inv_out[src] precomputed at fill
__device__ float g_bufA[(size_t)MAXN * DC];
__device__ float g_bufB[(size_t)MAXN * DC];
__device__ int   g_bsum[512];
__device__ int   g_bpre[512];

__device__ int            g_bar_count;
__device__ volatile int   g_bar_gen;

// ---------------- shared memory ----------------
struct SmemU {
    union {
        struct { float As[128 * APITCH]; float Bs[16 * BPITCH]; } g;  // 14.8 KB
        struct { int tmp[NTHR]; } s;
    };
};

// ---------------- grid-wide barrier ----------------
__device__ __forceinline__ void gsync() {
    __syncthreads();
    if (threadIdx.x == 0) {
        __threadfence();
        int gen = g_bar_gen;
        if (atomicAdd(&g_bar_count, 1) == (int)gridDim.x - 1) {
            g_bar_count = 0;
            __threadfence();
            g_bar_gen = gen + 1;
        } else {
            while (g_bar_gen == gen) { }
        }
    }
    __syncthreads();
}

__device__ __forceinline__ float tf32r(float x) {
    float y;
    asm("cvt.rna.tf32.f32 %0, %1;" : "=f"(y) : "f"(x));
    return y;
}

__device__ __forceinline__ void mma_tf32(float c[4], const unsigned a[4], const unsigned b[2]) {
    asm volatile(
        "mma.sync.aligned.m16n8k8.row.col.f32.tf32.tf32.f32 "
        "{%0,%1,%2,%3}, {%4,%5,%6,%7}, {%8,%9}, {%0,%1,%2,%3};"
        : "+f"(c[0]), "+f"(c[1]), "+f"(c[2]), "+f"(c[3])
        : "r"(a[0]), "r"(a[1]), "r"(a[2]), "r"(a[3]), "r"(b[0]), "r"(b[1]));
}

// ---------------- TF32 tensor-core GEMM stage (unchanged from R13) ----------------
__device__ void gemm_stage(const float* __restrict__ A, const float* __restrict__ W,
                           const float* __restrict__ bias, float* __restrict__ C,
                           int nrows, int din, int dout, int ldc, int coff,
                           int maskdeg, SmemU* sm) {
    const int BM = 128, BN = 64, BK = 16;
    int tid = threadIdx.x;
    int w = tid >> 5, lane = tid & 31;
    int tq = lane >> 2, tr = lane & 3;
    int woff = (w & 3) * 32;
    int noff = (w >> 2) * 32;

    int tilesX = (dout + BN - 1) / BN;
    int tilesY = (nrows + BM - 1) / BM;
    int numTiles = tilesX * tilesY;

    int la_r = tid >> 2;
    int la_k = (tid & 3) * 4;
    int lb_k = tid >> 4;
    int lb_c = (tid & 15) * 4;

    float* As = sm->g.As;
    float* Bs = sm->g.Bs;

    for (int t = blockIdx.x; t < numTiles; t += gridDim.x) {
        int bx = t % tilesX, by = t / tilesX;
        int row0 = by * BM, col0 = bx * BN;

        float acc[2][4][4];
        #pragma unroll
        for (int m = 0; m < 2; m++)
            #pragma unroll
            for (int j = 0; j < 4; j++)
                #pragma unroll
                for (int c = 0; c < 4; c++) acc[m][j][c] = 0.f;

        float4 pa[2], pb;
        {
            #pragma unroll
            for (int pass = 0; pass < 2; pass++) {
                int r = row0 + la_r + 64 * pass;
                pa[pass] = (r < nrows) ? *(const float4*)&A[(size_t)r * din + la_k]
                                       : make_float4(0.f, 0.f, 0.f, 0.f);
            }
            int cc = col0 + lb_c;
            pb = (cc + 3 < dout) ? *(const float4*)&W[(size_t)lb_k * dout + cc]
                                 : make_float4(0.f, 0.f, 0.f, 0.f);
        }

        for (int k0 = 0; k0 < din; k0 += BK) {
            __syncthreads();
            #pragma unroll
            for (int pass = 0; pass < 2; pass++) {
                int m = la_r + 64 * pass;
                As[m * APITCH + la_k + 0] = tf32r(pa[pass].x);
                As[m * APITCH + la_k + 1] = tf32r(pa[pass].y);
                As[m * APITCH + la_k + 2] = tf32r(pa[pass].z);
                As[m * APITCH + la_k + 3] = tf32r(pa[pass].w);
            }
            Bs[lb_k * BPITCH + lb_c + 0] = tf32r(pb.x);
            Bs[lb_k * BPITCH + lb_c + 1] = tf32r(pb.y);
            Bs[lb_k * BPITCH + lb_c + 2] = tf32r(pb.z);
            Bs[lb_k * BPITCH + lb_c + 3] = tf32r(pb.w);
            __syncthreads();

            if (k0 + BK < din) {
                #pragma unroll
                for (int pass = 0; pass < 2; pass++) {
                    int r = row0 + la_r + 64 * pass;
                    pa[pass] = (r < nrows)
                        ? *(const float4*)&A[(size_t)r * din + k0 + BK + la_k]
                        : make_float4(0.f, 0.f, 0.f, 0.f);
                }
                int cc = col0 + lb_c;
                pb = (cc + 3 < dout)
                    ? *(const float4*)&W[(size_t)(k0 + BK + lb_k) * dout + cc]
                    : make_float4(0.f, 0.f, 0.f, 0.f);
            }

            #pragma unroll
            for (int kc = 0; kc < BK; kc += 8) {
                unsigned a[2][4], b[4][2];
                #pragma unroll
                for (int m = 0; m < 2; m++) {
                    int br = woff + 16 * m + tq;
                    a[m][0] = __float_as_uint(As[br * APITCH + kc + tr]);
                    a[m][1] = __float_as_uint(As[(br + 8) * APITCH + kc + tr]);
                    a[m][2] = __float_as_uint(As[br * APITCH + kc + tr + 4]);
                    a[m][3] = __float_as_uint(As[(br + 8) * APITCH + kc + tr + 4]);
                }
                #pragma unroll
                for (int j = 0; j < 4; j++) {
                    int bn = noff + 8 * j + tq;
                    b[j][0] = __float_as_uint(Bs[(kc + tr) * BPITCH + bn]);
                    b[j][1] = __float_as_uint(Bs[(kc + tr + 4) * BPITCH + bn]);
                }
                #pragma unroll
                for (int m = 0; m < 2; m++)
                    #pragma unroll
                    for (int j = 0; j < 4; j++)
                        mma_tf32(acc[m][j], a[m], b[j]);
            }
        }
        __syncthreads();

        #pragma unroll
        for (int m = 0; m < 2; m++) {
            #pragma unroll
            for (int j = 0; j < 4; j++) {
                int cg = col0 + noff + 8 * j + 2 * tr;
                if (cg >= dout) continue;
                float b0 = bias[cg], b1 = bias[cg + 1];
                int rg = row0 + woff + 16 * m + tq;
                #pragma unroll
                for (int h = 0; h < 2; h++) {
                    int r = rg + 8 * h;
                    if (r < nrows) {
                        float scale = (maskdeg && g_deg_in[r] == 0) ? 0.f : 1.f;
                        float2 v;
                        v.x = scale * fmaxf(acc[m][j][2 * h + 0] + b0, 0.f);
                        v.y = scale * fmaxf(acc[m][j][2 * h + 1] + b1, 0.f);
                        *(float2*)&C[(size_t)r * ldc + coff + cg] = v;
                    }
                }
            }
        }
    }
}

// ---------------- conv aggregation, 4-edge unroll, precomputed weights ----------------
template <int ND>
__device__ __forceinline__ void conv_agg(const float* __restrict__ H, float* __restrict__ OUT,
                                         int n, int warp_g, int warps_total, int lane) {
    const int d = ND * 32;
    for (int v = warp_g; v < n; v += warps_total) {
        int start = g_off[v], end = g_off[v + 1];
        float acc[ND];
        #pragma unroll
        for (int i = 0; i < ND; i++) acc[i] = 0.f;
        int p = start;
        for (; p + 3 < end; p += 4) {
            int s0 = g_csr_src[p],     s1 = g_csr_src[p + 1];
            int s2 = g_csr_src[p + 2], s3 = g_csr_src[p + 3];
            float w0 = g_csr_w[p],     w1 = g_csr_w[p + 1];
            float w2 = g_csr_w[p + 2], w3 = g_csr_w[p + 3];
            const float* h0 = H + (size_t)s0 * d;
            const float* h1 = H + (size_t)s1 * d;
            const float* h2 = H + (size_t)s2 * d;
            const float* h3 = H + (size_t)s3 * d;
            #pragma unroll
            for (int i = 0; i < ND; i++) {
                int k = lane + 32 * i;
                acc[i] += h0[k] * w0 + h1[k] * w1 + h2[k] * w2 + h3[k] * w3;
            }
        }
        for (; p < end; p++) {
            int s0 = g_csr_src[p];
            float w0 = g_csr_w[p];
            const float* h0 = H + (size_t)s0 * d;
            #pragma unroll
            for (int i = 0; i < ND; i++)
                acc[i] += h0[lane + 32 * i] * w0;
        }
        float wi = g_inv_in[v];
        #pragma unroll
        for (int i = 0; i < ND; i++)
            OUT[(size_t)v * d + lane + 32 * i] = acc[i] * wi;
    }
}

// ---------------- fused persistent kernel ----------------
__global__ void __launch_bounds__(NTHR, 2)
fused_gnn(const float* __restrict__ node_feats, const float* __restrict__ edge_feats,
          const float* __restrict__ Wn, const float* __restrict__ bn,
          const float* __restrict__ We, const float* __restrict__ be,
          const float* __restrict__ Wc0, const float* __restrict__ bc0,
          const float* __restrict__ Wc1, const float* __restrict__ bc1,
          const float* __restrict__ Wl0, const float* __restrict__ bl0,
          const float* __restrict__ Wo, const float* __restrict__ bo,
          const int* __restrict__ src, const int* __restrict__ dst,
          float* __restrict__ out, int n, int e) {
    __shared__ SmemU sm;
    int tid = threadIdx.x;
    int gtid = blockIdx.x * NTHR + tid;
    int gstride = gridDim.x * NTHR;
    int w = tid >> 5, lane = tid & 31;
    int warp_g = blockIdx.x * 8 + w;
    int warps_total = gridDim.x * 8;
    int nchunks = (n + NTHR - 1) / NTHR;

    // ---- 1: zero degrees ----
    for (int i = gtid; i < n; i += gstride) { g_deg_in[i] = 0; g_deg_out[i] = 0; }
    gsync();

    // ---- 2: degree histogram ----
    for (int i = gtid; i < e; i += gstride) {
        atomicAdd(&g_deg_in[dst[i]], 1);
        atomicAdd(&g_deg_out[src[i]], 1);
    }
    gsync();

    // ---- 3: inv factors + per-chunk local scan ----
    for (int i = gtid; i < n; i += gstride) {
        int di = g_deg_in[i], dn = g_deg_out[i];
        g_inv_in[i]  = rsqrtf((float)(di > 1 ? di : 1));
        g_inv_out[i] = rsqrtf((float)(dn > 1 ? dn : 1));
    }
    if ((int)blockIdx.x < nchunks) {
        int i = blockIdx.x * NTHR + tid;
        int v = (i < n) ? g_deg_in[i] : 0;
        sm.s.tmp[tid] = v;
        __syncthreads();
        for (int ofs = 1; ofs < NTHR; ofs <<= 1) {
            int cur = sm.s.tmp[tid];
            int add = (tid >= ofs) ? sm.s.tmp[tid - ofs] : 0;
            __syncthreads();
            sm.s.tmp[tid] = cur + add;
            __syncthreads();
        }
        if (i < n) g_off[i] = sm.s.tmp[tid] - v;
        if (tid == NTHR - 1) g_bsum[blockIdx.x] = sm.s.tmp[tid];
    }
    gsync();

    // ---- 4: scan block sums (one warp) ----
    if (blockIdx.x == 0 && w == 0) {
        int carry = 0;
        for (int base = 0; base < nchunks; base += 32) {
            int idx = base + lane;
            int orig = (idx < nchunks) ? g_bsum[idx] : 0;
            int v = orig;
            #pragma unroll
            for (int o = 1; o < 32; o <<= 1) {
                int t = __shfl_up_sync(0xffffffffu, v, o);
                if (lane >= o) v += t;
            }
            if (idx < nchunks) g_bpre[idx] = carry + v - orig;
            carry += __shfl_sync(0xffffffffu, v, 31);
        }
    }
    gsync();

    // ---- 5: add block prefixes ----
    for (int i = gtid; i < n; i += gstride) {
        int o = g_off[i] + g_bpre[i / NTHR];
        g_off[i] = o;
        g_cursor[i] = o;
    }
    if (gtid == 0) g_off[n] = e;
    gsync();

    // ---- 6: CSR fill (+ precompute edge weight inv_out[src]) ----
    for (int i = gtid; i < e; i += gstride) {
        int d = dst[i];
        int s = src[i];
        int p = atomicAdd(&g_cursor[d], 1);
        g_csr_src[p] = s;
        g_csr_eid[p] = i;
        g_csr_w[p]   = g_inv_out[s];
    }
    gsync();

    // ---- 7: mean edge features -> bufB[v][0..31] (stride 32), 4-edge unroll ----
    for (int v = warp_g; v < n; v += warps_total) {
        int start = g_off[v], end = g_off[v + 1];
        float acc = 0.f;
        int p = start;
        for (; p + 3 < end; p += 4) {
            int e0 = g_csr_eid[p],     e1 = g_csr_eid[p + 1];
            int e2 = g_csr_eid[p + 2], e3 = g_csr_eid[p + 3];
            acc += edge_feats[(size_t)e0 * EDGE_IN + lane]
                 + edge_feats[(size_t)e1 * EDGE_IN + lane]
                 + edge_feats[(size_t)e2 * EDGE_IN + lane]
                 + edge_feats[(size_t)e3 * EDGE_IN + lane];
        }
        for (; p < end; p++)
            acc += edge_feats[(size_t)g_csr_eid[p] * EDGE_IN + lane];
        int c = end - start;
        g_bufB[(size_t)v * EDGE_IN + lane] = (c > 0) ? acc / (float)c : 0.f;
    }
    gsync();

    // ---- 8: edge GEMM (32->32, masked) + node GEMM (64->96) -> bufA ----
    gemm_stage(g_bufB, We, be, g_bufA, n, EDGE_IN, EDGE_OUT, D0, 0, 1, &sm);
    gemm_stage(node_feats, Wn, bn, g_bufA, n, NODE_IN, NODE_OUT, D0, EDGE_OUT, 0, &sm);
    gsync();

    // ---- 9: conv0 aggregation (d=128): bufA -> bufB ----
    conv_agg<4>(g_bufA, g_bufB, n, warp_g, warps_total, lane);
    gsync();

    // ---- 10: conv0 GEMM 128->192: bufB -> bufA ----
    gemm_stage(g_bufB, Wc0, bc0, g_bufA, n, D0, DC, DC, 0, 0, &sm);
    gsync();

    // ---- 11: conv1 aggregation (d=192): bufA -> bufB ----
    conv_agg<6>(g_bufA, g_bufB, n, warp_g, warps_total, lane);
    gsync();

    // ---- 12: conv1 GEMM 192->192: bufB -> bufA ----
    gemm_stage(g_bufB, Wc1, bc1, g_bufA, n, DC, DC, DC, 0, 0, &sm);
    gsync();

    // ---- 13: linear 192->192: bufA -> bufB ----
    gemm_stage(g_bufA, Wl0, bl0, g_bufB, n, DC, DC, DC, 0, 0, &sm);
    gsync();

    // ---- 14: output head 192->2 (exact fp32) ----
    for (int v = warp_g; v < n; v += warps_total) {
        const float* hp = g_bufB + (size_t)v * DC;
        float a0 = 0.f, a1 = 0.f;
        #pragma unroll
        for (int i = 0; i < DC / 32; i++) {
            int k = lane + 32 * i;
            float h = hp[k];
            a0 += h * Wo[k * 2 + 0];
            a1 += h * Wo[k * 2 + 1];
        }
        #pragma unroll
        for (int o = 16; o; o >>= 1) {
            a0 += __shfl_xor_sync(0xffffffffu, a0, o);
            a1 += __shfl_xor_sync(0xffffffffu, a1, o);
        }
        if (lane == 0) {
            out[(size_t)v * 2 + 0] = a0 + bo[0];
            out[(size_t)v * 2 + 1] = a1 + bo[1];
        }
    }
}

// ---------------- launch: ONE kernel ----------------
extern "C" void kernel_launch(void* const* d_in, const int* in_sizes, int n_in,
                              void* d_out, int out_size) {
    const float* node_feats = (const float*)d_in[0];
    const float* edge_feats = (const float*)d_in[1];
    const float* Wn  = (const float*)d_in[2];
    const float* bn  = (const float*)d_in[3];
    const float* We  = (const float*)d_in[4];
    const float* be  = (const float*)d_in[5];
    const float* Wc0 = (const float*)d_in[6];
    const float* bc0 = (const float*)d_in[7];
    const float* Wc1 = (const float*)d_in[8];
    const float* bc1 = (const float*)d_in[9];
    const float* Wl0 = (const float*)d_in[10];
    const float* bl0 = (const float*)d_in[11];
    const float* Wo  = (const float*)d_in[12];
    const float* bo  = (const float*)d_in[13];
    const int*   src = (const int*)d_in[14];
    const int*   dst = (const int*)d_in[15];
    float* out = (float*)d_out;

    int n = in_sizes[0] / NODE_IN;   // 50000
    int e = in_sizes[14];            // 800000

    fused_gnn<<<NBLK, NTHR>>>(node_feats, edge_feats, Wn, bn, We, be,
                              Wc0, bc0, Wc1, bc1, Wl0, bl0, Wo, bo,
                              src, dst, out, n, e);
}

// round 15
// speedup vs baseline: 2.6395x; 1.1533x over previous
#include <cuda_runtime.h>
#include <math.h>

#define NODE_IN 64
#define NODE_OUT 96
#define EDGE_IN 32
#define EDGE_OUT 32
#define D0 128
#define DC 192
#define NCLS 2
#define MAXN 50000
#define MAXE 800000

#define NBLK 444      // 3 CTAs/SM x 148 SMs -> co-resident (grid barrier safe)
#define NTHR 256

#define APITCH 20     // A smem pitch (floats): 16B-aligned rows, conflict-free frag reads
#define BPITCH 72     // B smem pitch (floats): conflict-free

// ---------------- device scratch ----------------
__device__ int   g_deg_in[MAXN];
__device__ int   g_deg_out[MAXN];
__device__ int   g_cursor[MAXN];
__device__ int   g_off[MAXN + 1];
__device__ float g_inv_in[MAXN];
__device__ float g_inv_out[MAXN];
__device__ int   g_csr_src[MAXE];
__device__ int   g_csr_eid[MAXE];
__device__ float g_csr_w[MAXE];      // inv_out[src] precomputed at fill
__device__ float g_bufA[(size_t)MAXN * DC];
__device__ float g_bufB[(size_t)MAXN * DC];
__device__ int   g_bsum[512];
__device__ int   g_bpre[512];

__device__ int            g_bar_count;
__device__ volatile int   g_bar_gen;

// ---------------- shared memory ----------------
struct SmemU {
    union {
        struct { float As[2][128 * APITCH]; float Bs[2][16 * BPITCH]; } g;  // ~29.7 KB
        struct { int tmp[NTHR]; } s;
    };
};

// ---------------- grid-wide barrier ----------------
__device__ __forceinline__ void gsync() {
    __syncthreads();
    if (threadIdx.x == 0) {
        __threadfence();
        int gen = g_bar_gen;
        if (atomicAdd(&g_bar_count, 1) == (int)gridDim.x - 1) {
            g_bar_count = 0;
            __threadfence();
            g_bar_gen = gen + 1;
        } else {
            while (g_bar_gen == gen) { }
        }
    }
    __syncthreads();
}

__device__ __forceinline__ void cp16(float* sdst, const float* gsrc, int valid) {
    unsigned sa = (unsigned)__cvta_generic_to_shared(sdst);
    int sz = valid ? 16 : 0;
    asm volatile("cp.async.cg.shared.global [%0], [%1], 16, %2;\n"
                 :: "r"(sa), "l"(gsrc), "r"(sz));
}
__device__ __forceinline__ void cp_commit() {
    asm volatile("cp.async.commit_group;\n");
}
template <int N>
__device__ __forceinline__ void cp_wait() {
    asm volatile("cp.async.wait_group %0;\n" :: "n"(N));
}

__device__ __forceinline__ void mma_tf32(float c[4], const unsigned a[4], const unsigned b[2]) {
    asm volatile(
        "mma.sync.aligned.m16n8k8.row.col.f32.tf32.tf32.f32 "
        "{%0,%1,%2,%3}, {%4,%5,%6,%7}, {%8,%9}, {%0,%1,%2,%3};"
        : "+f"(c[0]), "+f"(c[1]), "+f"(c[2]), "+f"(c[3])
        : "r"(a[0]), "r"(a[1]), "r"(a[2]), "r"(a[3]), "r"(b[0]), "r"(b[1]));
}

// ---------------- TF32 tensor-core GEMM stage (cp.async double-buffered) -------
// C[r, coff+c] = relu(A[r,:]@W[:,c] + bias[c]); maskdeg: zero rows with deg_in==0.
// din % 16 == 0; dout % 8 == 0. CTA tile 128x64, warp tile 32x32, k-step 16.
__device__ void gemm_stage(const float* __restrict__ A, const float* __restrict__ W,
                           const float* __restrict__ bias, float* __restrict__ C,
                           int nrows, int din, int dout, int ldc, int coff,
                           int maskdeg, SmemU* sm) {
    const int BM = 128, BN = 64, BK = 16;
    int tid = threadIdx.x;
    int w = tid >> 5, lane = tid & 31;
    int tq = lane >> 2, tr = lane & 3;
    int woff = (w & 3) * 32;
    int noff = (w >> 2) * 32;

    int tilesX = (dout + BN - 1) / BN;
    int tilesY = (nrows + BM - 1) / BM;
    int numTiles = tilesX * tilesY;

    // A loads: 512 16B-chunks (128 rows x 4), 2 per thread
    int lar0 = (tid * 2) >> 2;            // row of chunk0
    int lak0 = ((tid * 2) & 3) * 4;       // k-offset of chunk0
    int lar1 = (tid * 2 + 1) >> 2;
    int lak1 = ((tid * 2 + 1) & 3) * 4;
    // B loads: 256 chunks (16 k-rows x 16), 1 per thread
    int lbk = tid >> 4;
    int lbc = (tid & 15) * 4;

    for (int t = blockIdx.x; t < numTiles; t += gridDim.x) {
        int bx = t % tilesX, by = t / tilesX;
        int row0 = by * BM, col0 = bx * BN;
        int nt = din / BK;

        float acc[2][4][4];
        #pragma unroll
        for (int m = 0; m < 2; m++)
            #pragma unroll
            for (int j = 0; j < 4; j++)
                #pragma unroll
                for (int c = 0; c < 4; c++) acc[m][j][c] = 0.f;

        // prologue: issue tile 0 into buf 0
        {
            int r0 = row0 + lar0, r1 = row0 + lar1;
            cp16(&sm->g.As[0][lar0 * APITCH + lak0],
                 &A[(size_t)min(r0, nrows - 1) * din + lak0], r0 < nrows);
            cp16(&sm->g.As[0][lar1 * APITCH + lak1],
                 &A[(size_t)min(r1, nrows - 1) * din + lak1], r1 < nrows);
            int cc = col0 + lbc;
            cp16(&sm->g.Bs[0][lbk * BPITCH + lbc],
                 &W[(size_t)lbk * dout + min(cc, dout - 4)], cc + 3 < dout);
            cp_commit();
        }

        for (int it = 0; it < nt; it++) {
            int cur = it & 1;
            if (it + 1 < nt) {
                int nxt = cur ^ 1;
                int kb = (it + 1) * BK;
                int r0 = row0 + lar0, r1 = row0 + lar1;
                cp16(&sm->g.As[nxt][lar0 * APITCH + lak0],
                     &A[(size_t)min(r0, nrows - 1) * din + kb + lak0], r0 < nrows);
                cp16(&sm->g.As[nxt][lar1 * APITCH + lak1],
                     &A[(size_t)min(r1, nrows - 1) * din + kb + lak1], r1 < nrows);
                int cc = col0 + lbc;
                cp16(&sm->g.Bs[nxt][(lbk)*BPITCH + lbc],
                     &W[(size_t)(kb + lbk) * dout + min(cc, dout - 4)], cc + 3 < dout);
                cp_commit();
                cp_wait<1>();
            } else {
                cp_wait<0>();
            }
            __syncthreads();

            const float* As = sm->g.As[cur];
            const float* Bs = sm->g.Bs[cur];
            #pragma unroll
            for (int kc = 0; kc < BK; kc += 8) {
                unsigned a[2][4], b[4][2];
                #pragma unroll
                for (int m = 0; m < 2; m++) {
                    int br = woff + 16 * m + tq;
                    a[m][0] = __float_as_uint(As[br * APITCH + kc + tr]);
                    a[m][1] = __float_as_uint(As[(br + 8) * APITCH + kc + tr]);
                    a[m][2] = __float_as_uint(As[br * APITCH + kc + tr + 4]);
                    a[m][3] = __float_as_uint(As[(br + 8) * APITCH + kc + tr + 4]);
                }
                #pragma unroll
                for (int j = 0; j < 4; j++) {
                    int bn = noff + 8 * j + tq;
                    b[j][0] = __float_as_uint(Bs[(kc + tr) * BPITCH + bn]);
                    b[j][1] = __float_as_uint(Bs[(kc + tr + 4) * BPITCH + bn]);
                }
                #pragma unroll
                for (int m = 0; m < 2; m++)
                    #pragma unroll
                    for (int j = 0; j < 4; j++)
                        mma_tf32(acc[m][j], a[m], b[j]);
            }
            __syncthreads();   // compute done before next prefetch overwrites this buf
        }

        // epilogue
        #pragma unroll
        for (int m = 0; m < 2; m++) {
            #pragma unroll
            for (int j = 0; j < 4; j++) {
                int cg = col0 + noff + 8 * j + 2 * tr;
                if (cg >= dout) continue;
                float b0 = bias[cg], b1 = bias[cg + 1];
                int rg = row0 + woff + 16 * m + tq;
                #pragma unroll
                for (int h = 0; h < 2; h++) {
                    int r = rg + 8 * h;
                    if (r < nrows) {
                        float scale = (maskdeg && g_deg_in[r] == 0) ? 0.f : 1.f;
                        float2 v;
                        v.x = scale * fmaxf(acc[m][j][2 * h + 0] + b0, 0.f);
                        v.y = scale * fmaxf(acc[m][j][2 * h + 1] + b1, 0.f);
                        *(float2*)&C[(size_t)r * ldc + coff + cg] = v;
                    }
                }
            }
        }
    }
}

// ---------------- conv aggregation, 4-edge unroll, precomputed weights ----------------
template <int ND>
__device__ __forceinline__ void conv_agg(const float* __restrict__ H, float* __restrict__ OUT,
                                         int n, int warp_g, int warps_total, int lane) {
    const int d = ND * 32;
    for (int v = warp_g; v < n; v += warps_total) {
        int start = g_off[v], end = g_off[v + 1];
        float acc[ND];
        #pragma unroll
        for (int i = 0; i < ND; i++) acc[i] = 0.f;
        int p = start;
        for (; p + 3 < end; p += 4) {
            int s0 = g_csr_src[p],     s1 = g_csr_src[p + 1];
            int s2 = g_csr_src[p + 2], s3 = g_csr_src[p + 3];
            float w0 = g_csr_w[p],     w1 = g_csr_w[p + 1];
            float w2 = g_csr_w[p + 2], w3 = g_csr_w[p + 3];
            const float* h0 = H + (size_t)s0 * d;
            const float* h1 = H + (size_t)s1 * d;
            const float* h2 = H + (size_t)s2 * d;
            const float* h3 = H + (size_t)s3 * d;
            #pragma unroll
            for (int i = 0; i < ND; i++) {
                int k = lane + 32 * i;
                acc[i] += h0[k] * w0 + h1[k] * w1 + h2[k] * w2 + h3[k] * w3;
            }
        }
        for (; p < end; p++) {
            int s0 = g_csr_src[p];
            float w0 = g_csr_w[p];
            const float* h0 = H + (size_t)s0 * d;
            #pragma unroll
            for (int i = 0; i < ND; i++)
                acc[i] += h0[lane + 32 * i] * w0;
        }
        float wi = g_inv_in[v];
        #pragma unroll
        for (int i = 0; i < ND; i++)
            OUT[(size_t)v * d + lane + 32 * i] = acc[i] * wi;
    }
}

// ---------------- fused persistent kernel ----------------
__global__ void __launch_bounds__(NTHR, 3)
fused_gnn(const float* __restrict__ node_feats, const float* __restrict__ edge_feats,
          const float* __restrict__ Wn, const float* __restrict__ bn,
          const float* __restrict__ We, const float* __restrict__ be,
          const float* __restrict__ Wc0, const float* __restrict__ bc0,
          const float* __restrict__ Wc1, const float* __restrict__ bc1,
          const float* __restrict__ Wl0, const float* __restrict__ bl0,
          const float* __restrict__ Wo, const float* __restrict__ bo,
          const int* __restrict__ src, const int* __restrict__ dst,
          float* __restrict__ out, int n, int e) {
    __shared__ SmemU sm;
    int tid = threadIdx.x;
    int gtid = blockIdx.x * NTHR + tid;
    int gstride = gridDim.x * NTHR;
    int w = tid >> 5, lane = tid & 31;
    int warp_g = blockIdx.x * 8 + w;
    int warps_total = gridDim.x * 8;
    int nchunks = (n + NTHR - 1) / NTHR;

    // ---- 1: zero degrees ----
    for (int i = gtid; i < n; i += gstride) { g_deg_in[i] = 0; g_deg_out[i] = 0; }
    gsync();

    // ---- 2: degree histogram ----
    for (int i = gtid; i < e; i += gstride) {
        atomicAdd(&g_deg_in[dst[i]], 1);
        atomicAdd(&g_deg_out[src[i]], 1);
    }
    gsync();

    // ---- 3: inv factors + per-chunk local scan ----
    for (int i = gtid; i < n; i += gstride) {
        int di = g_deg_in[i], dn = g_deg_out[i];
        g_inv_in[i]  = rsqrtf((float)(di > 1 ? di : 1));
        g_inv_out[i] = rsqrtf((float)(dn > 1 ? dn : 1));
    }
    if ((int)blockIdx.x < nchunks) {
        int i = blockIdx.x * NTHR + tid;
        int v = (i < n) ? g_deg_in[i] : 0;
        sm.s.tmp[tid] = v;
        __syncthreads();
        for (int ofs = 1; ofs < NTHR; ofs <<= 1) {
            int cur = sm.s.tmp[tid];
            int add = (tid >= ofs) ? sm.s.tmp[tid - ofs] : 0;
            __syncthreads();
            sm.s.tmp[tid] = cur + add;
            __syncthreads();
        }
        if (i < n) g_off[i] = sm.s.tmp[tid] - v;
        if (tid == NTHR - 1) g_bsum[blockIdx.x] = sm.s.tmp[tid];
    }
    gsync();

    // ---- 4: scan block sums (one warp) ----
    if (blockIdx.x == 0 && w == 0) {
        int carry = 0;
        for (int base = 0; base < nchunks; base += 32) {
            int idx = base + lane;
            int orig = (idx < nchunks) ? g_bsum[idx] : 0;
            int v = orig;
            #pragma unroll
            for (int o = 1; o < 32; o <<= 1) {
                int t = __shfl_up_sync(0xffffffffu, v, o);
                if (lane >= o) v += t;
            }
            if (idx < nchunks) g_bpre[idx] = carry + v - orig;
            carry += __shfl_sync(0xffffffffu, v, 31);
        }
    }
    gsync();

    // ---- 5: add block prefixes ----
    for (int i = gtid; i < n; i += gstride) {
        int o = g_off[i] + g_bpre[i / NTHR];
        g_off[i] = o;
        g_cursor[i] = o;
    }
    if (gtid == 0) g_off[n] = e;
    gsync();

    // ---- 6: CSR fill (+ precompute edge weight inv_out[src]) ----
    for (int i = gtid; i < e; i += gstride) {
        int d = dst[i];
        int s = src[i];
        int p = atomicAdd(&g_cursor[d], 1);
        g_csr_src[p] = s;
        g_csr_eid[p] = i;
        g_csr_w[p]   = g_inv_out[s];
    }
    gsync();

    // ---- 7: mean edge features -> bufB[v][0..31] (stride 32), 4-edge unroll ----
    for (int v = warp_g; v < n; v += warps_total) {
        int start = g_off[v], end = g_off[v + 1];
        float acc = 0.f;
        int p = start;
        for (; p + 3 < end; p += 4) {
            int e0 = g_csr_eid[p],     e1 = g_csr_eid[p + 1];
            int e2 = g_csr_eid[p + 2], e3 = g_csr_eid[p + 3];
            acc += edge_feats[(size_t)e0 * EDGE_IN + lane]
                 + edge_feats[(size_t)e1 * EDGE_IN + lane]
                 + edge_feats[(size_t)e2 * EDGE_IN + lane]
                 + edge_feats[(size_t)e3 * EDGE_IN + lane];
        }
        for (; p < end; p++)
            acc += edge_feats[(size_t)g_csr_eid[p] * EDGE_IN + lane];
        int c = end - start;
        g_bufB[(size_t)v * EDGE_IN + lane] = (c > 0) ? acc / (float)c : 0.f;
    }
    gsync();

    // ---- 8: edge GEMM (32->32, masked) + node GEMM (64->96) -> bufA ----
    gemm_stage(g_bufB, We, be, g_bufA, n, EDGE_IN, EDGE_OUT, D0, 0, 1, &sm);
    gemm_stage(node_feats, Wn, bn, g_bufA, n, NODE_IN, NODE_OUT, D0, EDGE_OUT, 0, &sm);
    gsync();

    // ---- 9: conv0 aggregation (d=128): bufA -> bufB ----
    conv_agg<4>(g_bufA, g_bufB, n, warp_g, warps_total, lane);
    gsync();

    // ---- 10: conv0 GEMM 128->192: bufB -> bufA ----
    gemm_stage(g_bufB, Wc0, bc0, g_bufA, n, D0, DC, DC, 0, 0, &sm);
    gsync();

    // ---- 11: conv1 aggregation (d=192): bufA -> bufB ----
    conv_agg<6>(g_bufA, g_bufB, n, warp_g, warps_total, lane);
    gsync();

    // ---- 12: conv1 GEMM 192->192: bufB -> bufA ----
    gemm_stage(g_bufB, Wc1, bc1, g_bufA, n, DC, DC, DC, 0, 0, &sm);
    gsync();

    // ---- 13: linear 192->192: bufA -> bufB ----
    gemm_stage(g_bufA, Wl0, bl0, g_bufB, n, DC, DC, DC, 0, 0, &sm);
    gsync();

    // ---- 14: output head 192->2 (exact fp32) ----
    for (int v = warp_g; v < n; v += warps_total) {
        const float* hp = g_bufB + (size_t)v * DC;
        float a0 = 0.f, a1 = 0.f;
        #pragma unroll
        for (int i = 0; i < DC / 32; i++) {
            int k = lane + 32 * i;
            float h = hp[k];
            a0 += h * Wo[k * 2 + 0];
            a1 += h * Wo[k * 2 + 1];
        }
        #pragma unroll
        for (int o = 16; o; o >>= 1) {
            a0 += __shfl_xor_sync(0xffffffffu, a0, o);
            a1 += __shfl_xor_sync(0xffffffffu, a1, o);
        }
        if (lane == 0) {
            out[(size_t)v * 2 + 0] = a0 + bo[0];
            out[(size_t)v * 2 + 1] = a1 + bo[1];
        }
    }
}

// ---------------- launch: ONE kernel ----------------
extern "C" void kernel_launch(void* const* d_in, const int* in_sizes, int n_in,
                              void* d_out, int out_size) {
    const float* node_feats = (const float*)d_in[0];
    const float* edge_feats = (const float*)d_in[1];
    const float* Wn  = (const float*)d_in[2];
    const float* bn  = (const float*)d_in[3];
    const float* We  = (const float*)d_in[4];
    const float* be  = (const float*)d_in[5];
    const float* Wc0 = (const float*)d_in[6];
    const float* bc0 = (const float*)d_in[7];
    const float* Wc1 = (const float*)d_in[8];
    const float* bc1 = (const float*)d_in[9];
    const float* Wl0 = (const float*)d_in[10];
    const float* bl0 = (const float*)d_in[11];
    const float* Wo  = (const float*)d_in[12];
    const float* bo  = (const float*)d_in[13];
    const int*   src = (const int*)d_in[14];
    const int*   dst = (const int*)d_in[15];
    float* out = (float*)d_out;

    int n = in_sizes[0] / NODE_IN;   // 50000
    int e = in_sizes[14];            // 800000

    fused_gnn<<<NBLK, NTHR>>>(node_feats, edge_feats, Wn, bn, We, be,
                              Wc0, bc0, Wc1, bc1, Wl0, bl0, Wo, bo,
                              src, dst, out, n, e);
}